// round 16
// baseline (speedup 1.0000x reference)
#include <cuda_runtime.h>
#include <cuda_bf16.h>
#include <math.h>
#include <stdint.h>

#define BQ    1024
#define NM    50000
#define DD    256
#define MAXA  200
#define KSEL  8
#define NSPLIT 37
#define SPLEN  1352            // ceil(50000/37)
#define CPS   32               // candidates per (query, split): 8 threads x top-4
#define NC2   (NSPLIT*CPS)     // 1184 candidates per query at merge
#define RCAP  64               // refine-list capacity
#define MARGIN 4.25f           // approx err (~1.5) *2 + quantization slack
#define BIGF  3.0e38f

// -------- device scratch --------
__device__ unsigned g_mem_hi[NM * 128];   // bf16x2: col pair per u32
__device__ unsigned g_mem_lo[NM * 128];
__device__ unsigned g_q_hi[BQ * 128];
__device__ unsigned g_q_lo[BQ * 128];
__device__ float    g_mem_sq[NM];
__device__ float    g_q_sq[BQ];
__device__ uint32_t g_cand[BQ * NC2];     // packed: arg-bits[31:11] | m_rel[10:0]
__device__ float    g_h_mem[NM * 256];    // tanh(xW+b) fp32
__device__ float    g_h_q[BQ * 256];
// tf32 transform pipeline scratch
__device__ float    g_xp_mem[NM * 512];   // tf32 hi/lo pairs, k-permuted
__device__ float    g_xp_q[BQ * 512];
__device__ float    g_wp[256 * 512];      // W^T, tf32 hi/lo pairs, k-permuted

// ===================== PTX helpers =====================
__device__ __forceinline__ uint32_t smem_u32(const void* p) {
    uint32_t a;
    asm("{ .reg .u64 t; cvta.to.shared.u64 t, %1; cvt.u32.u64 %0, t; }" : "=r"(a) : "l"(p));
    return a;
}
#define LDSM_X4(r0, r1, r2, r3, addr) \
    asm volatile("ldmatrix.sync.aligned.m8n8.x4.shared.b16 {%0,%1,%2,%3}, [%4];" \
        : "=r"(r0), "=r"(r1), "=r"(r2), "=r"(r3) : "r"(addr))

__device__ __forceinline__ void mma_bf16(float* c, const uint32_t* a,
                                         uint32_t b0, uint32_t b1) {
    asm volatile("mma.sync.aligned.m16n8k16.row.col.f32.bf16.bf16.f32 "
        "{%0,%1,%2,%3},{%4,%5,%6,%7},{%8,%9},{%0,%1,%2,%3};"
        : "+f"(c[0]), "+f"(c[1]), "+f"(c[2]), "+f"(c[3])
        : "r"(a[0]), "r"(a[1]), "r"(a[2]), "r"(a[3]), "r"(b0), "r"(b1));
}
__device__ __forceinline__ void mma_tf32(float* c,
                                         uint32_t a0, uint32_t a1, uint32_t a2, uint32_t a3,
                                         uint32_t b0, uint32_t b1) {
    asm volatile("mma.sync.aligned.m16n8k8.row.col.f32.tf32.tf32.f32 "
        "{%0,%1,%2,%3},{%4,%5,%6,%7},{%8,%9},{%0,%1,%2,%3};"
        : "+f"(c[0]), "+f"(c[1]), "+f"(c[2]), "+f"(c[3])
        : "r"(a0), "r"(a1), "r"(a2), "r"(a3), "r"(b0), "r"(b1));
}
__device__ __forceinline__ float tf32f(float x) {
    uint32_t u;
    asm("cvt.rna.tf32.f32 %0, %1;" : "=r"(u) : "f"(x));
    return __uint_as_float(u);
}
// cp.async 16B with predicate zero-fill
__device__ __forceinline__ void cp_async16(uint32_t smem_addr, const void* gptr, bool pred) {
    int sz = pred ? 16 : 0;
    asm volatile("cp.async.cg.shared.global [%0], [%1], 16, %2;"
                 :: "r"(smem_addr), "l"(gptr), "r"(sz) : "memory");
}
#define CP_COMMIT() asm volatile("cp.async.commit_group;" ::: "memory")
#define CP_WAIT1()  asm volatile("cp.async.wait_group 1;" ::: "memory")
#define CP_WAIT0()  asm volatile("cp.async.wait_group 0;" ::: "memory")

// bf16x2 unpack: even dim in low 16 bits, odd dim in high 16 bits
__device__ __forceinline__ float bflo(uint32_t v) { return __uint_as_float(v << 16); }
__device__ __forceinline__ float bfhi(uint32_t v) { return __uint_as_float(v & 0xffff0000u); }

// ============================================================
// Pre-split kernels: fp32 -> tf32 (hi,lo) pairs, k-permuted pair layout.
// ============================================================
__device__ __forceinline__ int pair_pos(int kk) {   // kk = k & 15
    return ((kk >> 3) << 4) + (((kk >> 2) & 1) << 1) + ((kk & 3) << 2);
}

__global__ void presplit_x_kernel(const float* __restrict__ src,
                                  float* __restrict__ dst, int M)
{
    int idx = blockIdx.x * blockDim.x + threadIdx.x;   // one per 4 consecutive k
    int total = M * 64;
    if (idx >= total) return;
    int row = idx >> 6;
    int kq = (idx & 63) * 4;
    float4 v = *(const float4*)&src[row * 256 + kq];
    float vv[4] = {v.x, v.y, v.z, v.w};
    int base = row * 512 + (kq >> 4) * 32 + pair_pos(kq & 15);
#pragma unroll
    for (int e = 0; e < 4; e++) {
        float hi = tf32f(vv[e]);
        float lo = tf32f(vv[e] - hi);
        *(float2*)&dst[base + e * 4] = make_float2(hi, lo);
    }
}

__global__ void presplit_w_kernel(const float* __restrict__ W)
{
    int idx = blockIdx.x * blockDim.x + threadIdx.x;   // one per 4 consecutive cols
    if (idx >= 256 * 64) return;
    int k = idx >> 6;
    int c4 = (idx & 63) * 4;
    float4 v = *(const float4*)&W[k * 256 + c4];
    float vv[4] = {v.x, v.y, v.z, v.w};
    int pp = (k >> 4) * 32 + pair_pos(k & 15);
#pragma unroll
    for (int e = 0; e < 4; e++) {
        float hi = tf32f(vv[e]);
        float lo = tf32f(vv[e] - hi);
        *(float2*)&g_wp[(c4 + e) * 512 + pp] = make_float2(hi, lo);
    }
}

// ============================================================
// Kernel 1a: tf32 3-term GEMM + tanh with cp.async DOUBLE-BUFFERED fills.
// CTA 128 rows x 64 cols, 8 warps, BK=16, 2 smem buffers.
// ============================================================
#define GQS   4608                 // floats per QS buf (128*36)
#define GMS   2304                 // floats per MS buf (64*36)
#define GBUF  (GQS + GMS)          // 6912 floats = 27648 B
#define GSM_BYTES (2 * GBUF * 4)   // 55296

__device__ __forceinline__ void gemm_issue(uint32_t sQ, uint32_t sM,
                                           const float* __restrict__ Xp,
                                           int q0, int c0, int kc, int M, int tid)
{
#pragma unroll
    for (int it = 0; it < 4; it++) {
        int idx = tid + 256 * it;
        int r = idx >> 3, f4 = idx & 7;
        int row = q0 + r;
        const float* src = &Xp[(size_t)(row < M ? row : (M - 1)) * 512 + kc * 32 + f4 * 4];
        cp_async16(sQ + (uint32_t)(r * 36 + f4 * 4) * 4, src, row < M);
    }
#pragma unroll
    for (int it = 0; it < 2; it++) {
        int idx = tid + 256 * it;
        int r = idx >> 3, f4 = idx & 7;
        const float* src = &g_wp[(size_t)(c0 + r) * 512 + kc * 32 + f4 * 4];
        cp_async16(sM + (uint32_t)(r * 36 + f4 * 4) * 4, src, true);
    }
}

__global__ __launch_bounds__(256, 2)
void gemm_tanh_kernel(const float* __restrict__ Xp, const float* __restrict__ bias,
                      float* __restrict__ H, int M)
{
    extern __shared__ float gds[];
    __shared__ float sbias[64];
    const uint32_t sbase = smem_u32(gds);

    const int tid = threadIdx.x;
    const int lane = tid & 31;
    const int wid = tid >> 5;
    const int warp_q = wid & 3;
    const int warp_m = wid >> 2;
    const int g4 = lane >> 2;
    const int tg = lane & 3;

    const int q0 = blockIdx.x * 128;
    const int c0 = blockIdx.y * 64;

    if (tid < 64) sbias[tid] = bias[c0 + tid];

    float acc[2][4][4];
#pragma unroll
    for (int i = 0; i < 2; i++)
#pragma unroll
        for (int j = 0; j < 4; j++)
#pragma unroll
            for (int c = 0; c < 4; c++) acc[i][j][c] = 0.f;

    // prologue: chunk 0 into buf 0
    gemm_issue(sbase, sbase + GQS * 4, Xp, q0, c0, 0, M, tid);
    CP_COMMIT();

    for (int kc = 0; kc < 16; kc++) {
        const int cur = kc & 1;
        if (kc < 15) {
            uint32_t b = sbase + (uint32_t)(cur ^ 1) * (GBUF * 4);
            gemm_issue(b, b + GQS * 4, Xp, q0, c0, kc + 1, M, tid);
            CP_COMMIT();
            CP_WAIT1();
        } else {
            CP_WAIT0();
        }
        __syncthreads();

        const float* QS = gds + cur * GBUF;
        const float* MS = QS + GQS;
#pragma unroll
        for (int s = 0; s < 2; s++) {
            const int off = s * 16 + tg * 4;
            uint32_t ah[2][4], al[2][4];
#pragma unroll
            for (int i = 0; i < 2; i++) {
                int qr = warp_q * 32 + i * 16 + g4;
                float4 p0 = *(const float4*)&QS[qr * 36 + off];
                float4 p1 = *(const float4*)&QS[(qr + 8) * 36 + off];
                ah[i][0] = __float_as_uint(p0.x); al[i][0] = __float_as_uint(p0.y);
                ah[i][2] = __float_as_uint(p0.z); al[i][2] = __float_as_uint(p0.w);
                ah[i][1] = __float_as_uint(p1.x); al[i][1] = __float_as_uint(p1.y);
                ah[i][3] = __float_as_uint(p1.z); al[i][3] = __float_as_uint(p1.w);
            }
            uint32_t bh[4][2], bl[4][2];
#pragma unroll
            for (int j = 0; j < 4; j++) {
                int mr = warp_m * 32 + j * 8 + g4;
                float4 p = *(const float4*)&MS[mr * 36 + off];
                bh[j][0] = __float_as_uint(p.x); bl[j][0] = __float_as_uint(p.y);
                bh[j][1] = __float_as_uint(p.z); bl[j][1] = __float_as_uint(p.w);
            }
#pragma unroll
            for (int i = 0; i < 2; i++)
#pragma unroll
                for (int j = 0; j < 4; j++) {
                    mma_tf32(acc[i][j], ah[i][0], ah[i][1], ah[i][2], ah[i][3],
                             bh[j][0], bh[j][1]);
                    mma_tf32(acc[i][j], ah[i][0], ah[i][1], ah[i][2], ah[i][3],
                             bl[j][0], bl[j][1]);
                    mma_tf32(acc[i][j], al[i][0], al[i][1], al[i][2], al[i][3],
                             bh[j][0], bh[j][1]);
                }
        }
        __syncthreads();
    }

    // epilogue: bias + tanh -> smem stage (overlays buffers) -> coalesced write
    float* HS = gds;   // 128*68 floats = 34816 B < 55296 B
#pragma unroll
    for (int i = 0; i < 2; i++)
#pragma unroll
        for (int r = 0; r < 2; r++) {
            int q = warp_q * 32 + i * 16 + r * 8 + g4;
#pragma unroll
            for (int j = 0; j < 4; j++) {
                int ml = warp_m * 32 + j * 8 + 2 * tg;
                float vA = tanhf(acc[i][j][r * 2 + 0] + sbias[ml]);
                float vB = tanhf(acc[i][j][r * 2 + 1] + sbias[ml + 1]);
                *(float2*)&HS[q * 68 + ml] = make_float2(vA, vB);
            }
        }
    __syncthreads();

#pragma unroll
    for (int it = 0; it < 8; it++) {
        int idx = tid + 256 * it;
        int row = idx >> 4, f4 = idx & 15;
        if (q0 + row < M)
            *(float4*)&H[(size_t)(q0 + row) * DD + c0 + f4 * 4] =
                *(const float4*)&HS[row * 68 + f4 * 4];
    }
}

// ============================================================
// Kernel 1b: Norm/rescale/split (row stride 128 — FIXED).
// ============================================================
__global__ void norm_split_kernel(const float* __restrict__ H,
                                  unsigned* __restrict__ Hhi, unsigned* __restrict__ Hlo,
                                  float* __restrict__ SQ, int M)
{
    const int lane = threadIdx.x & 31;
    const int wid = threadIdx.x >> 5;
    const int row = blockIdx.x * 8 + wid;
    if (row >= M) return;

    float4 a = *(const float4*)&H[(size_t)row * 256 + lane * 8];
    float4 b = *(const float4*)&H[(size_t)row * 256 + lane * 8 + 4];
    float ss = a.x * a.x + a.y * a.y + a.z * a.z + a.w * a.w
             + b.x * b.x + b.y * b.y + b.z * b.z + b.w * b.w;
#pragma unroll
    for (int off = 16; off; off >>= 1)
        ss += __shfl_xor_sync(0xffffffffu, ss, off);

    float norm = sqrtf(ss);
    float sc = (norm > 0.95f) ? 0.95f / norm : 1.0f;
    if (lane == 0) SQ[row] = ss * sc * sc;

    float v[8] = {a.x * sc, a.y * sc, a.z * sc, a.w * sc,
                  b.x * sc, b.y * sc, b.z * sc, b.w * sc};
    uint32_t hiw[4], low[4];
#pragma unroll
    for (int p = 0; p < 4; p++) {
        float vx = v[2 * p], vy = v[2 * p + 1];
        __nv_bfloat16 hx = __float2bfloat16(vx);
        __nv_bfloat16 hy = __float2bfloat16(vy);
        __nv_bfloat16 lx = __float2bfloat16(vx - __bfloat162float(hx));
        __nv_bfloat16 ly = __float2bfloat16(vy - __bfloat162float(hy));
        hiw[p] = ((unsigned)__bfloat16_as_ushort(hy) << 16) | __bfloat16_as_ushort(hx);
        low[p] = ((unsigned)__bfloat16_as_ushort(ly) << 16) | __bfloat16_as_ushort(lx);
    }
    *(uint4*)&Hhi[(size_t)row * 128 + lane * 4] = make_uint4(hiw[0], hiw[1], hiw[2], hiw[3]);
    *(uint4*)&Hlo[(size_t)row * 128 + lane * 4] = make_uint4(low[0], low[1], low[2], low[3]);
}

// ============================================================
// Kernel 2: bf16 hi-only mma pruning pass (M-fill now cp.async; otherwise
// identical to the passing R14 kernel).
// ============================================================
#define RS       144
#define QCH_B    (128 * RS)
#define MCH_B    (64 * RS)
#define OFF_Q    0
#define OFF_M    (4 * QCH_B)
#define OFF_YS   (OFF_M + 4 * MCH_B)
#define OFF_RY   (OFF_YS + 256)
#define DSMEM_SZ (OFF_RY + 256)

__device__ __forceinline__ void ins4u(uint32_t (&la)[4], uint32_t& worst, uint32_t pk) {
    int mp = 0; uint32_t mv = la[0];
    if (la[1] > mv) { mv = la[1]; mp = 1; }
    if (la[2] > mv) { mv = la[2]; mp = 2; }
    if (la[3] > mv) { mv = la[3]; mp = 3; }
    la[mp] = pk;
    mv = la[0];
    if (la[1] > mv) mv = la[1];
    if (la[2] > mv) mv = la[2];
    if (la[3] > mv) mv = la[3];
    worst = mv;
}

__global__ __launch_bounds__(256, 2)
void dist_topk_kernel()
{
    extern __shared__ char sb[];
    const uint32_t sbase = smem_u32(sb);
    float* tYS = (float*)(sb + OFF_YS);
    float* tRY = (float*)(sb + OFF_RY);

    const int tid = threadIdx.x;
    const int lane = tid & 31;
    const int wid = tid >> 5;
    const int warp_q = wid & 3;
    const int warp_m = wid >> 2;
    const int g4 = lane >> 2;
    const int tg = lane & 3;

    const int q0 = blockIdx.x * 128;
    const int mstart = blockIdx.y * SPLEN;
    const int mend = min(mstart + SPLEN, NM);

    const uint32_t aOff = (uint32_t)((warp_q * 32 + (lane & 7) + ((lane >> 3) & 1) * 8) * RS
                                     + (((lane >> 4) & 1) * 8) * 2);
    const uint32_t bOff = (uint32_t)((warp_m * 32 + (lane & 7) + ((lane >> 4) & 1) * 8) * RS
                                     + (((lane >> 3) & 1) * 8) * 2);
    const uint32_t u_q = sbase + OFF_Q;
    const uint32_t u_m = sbase + OFF_M;

    float xs[2][2], cA[2][2];
#pragma unroll
    for (int i = 0; i < 2; i++)
#pragma unroll
        for (int r = 0; r < 2; r++) {
            float v = g_q_sq[q0 + warp_q * 32 + i * 16 + r * 8 + g4];
            xs[i][r] = v;
            cA[i][r] = 2.0f / (1.0f - v);
        }

    uint32_t la[2][2][4];
    uint32_t lw[2][2];
#pragma unroll
    for (int i = 0; i < 2; i++)
#pragma unroll
        for (int r = 0; r < 2; r++) {
            lw[i][r] = 0xFFFFFFFFu;
#pragma unroll
            for (int l = 0; l < 4; l++) la[i][r][l] = 0xFFFFFFFFu;
        }

    {
        const uint4* pQH = (const uint4*)g_q_hi;
#pragma unroll
        for (int it = 0; it < 16; it++) {
            int idx = tid + 256 * it;
            int r = idx >> 5, u = idx & 31;
            int chunk = u >> 3, kb = u & 7;
            uint4 v = pQH[(size_t)(q0 + r) * 32 + u];
            *(uint4*)(sb + OFF_Q + chunk * QCH_B + r * RS + kb * 16) = v;
        }
    }

    const uint4* pMH = (const uint4*)g_mem_hi;

    for (int m0 = mstart; m0 < mend; m0 += 64) {
        __syncthreads();

        if (tid < 64) {
            int m = m0 + tid;
            float ys = (m < mend) ? g_mem_sq[m] : 0.f;
            tYS[tid] = ys;
            tRY[tid] = __frcp_rn(1.0f - ys);
        }
#pragma unroll
        for (int it = 0; it < 8; it++) {
            int idx = tid + 256 * it;
            int r = idx >> 5, u = idx & 31;
            int chunk = u >> 3, kb = u & 7;
            int row = m0 + r;
            const uint4* src = &pMH[(size_t)(row < mend ? row : (mend - 1)) * 32 + u];
            cp_async16(u_m + (uint32_t)(chunk * MCH_B + r * RS + kb * 16), src, row < mend);
        }
        CP_COMMIT();
        CP_WAIT0();
        __syncthreads();

        float acc[2][4][4];
#pragma unroll
        for (int i = 0; i < 2; i++)
#pragma unroll
            for (int j = 0; j < 4; j++)
#pragma unroll
                for (int c = 0; c < 4; c++) acc[i][j][c] = 0.f;

#pragma unroll
        for (int c = 0; c < 4; c++) {
            const uint32_t aBase = u_q + c * QCH_B + aOff;
            const uint32_t bBase = u_m + c * MCH_B + bOff;
#pragma unroll
            for (int ks = 0; ks < 4; ks++) {
                uint32_t ah[2][4], bh[2][4];
#pragma unroll
                for (int i = 0; i < 2; i++)
                    LDSM_X4(ah[i][0], ah[i][1], ah[i][2], ah[i][3],
                            aBase + ks * 32 + i * (16 * RS));
#pragma unroll
                for (int jj = 0; jj < 2; jj++)
                    LDSM_X4(bh[jj][0], bh[jj][1], bh[jj][2], bh[jj][3],
                            bBase + ks * 32 + jj * (16 * RS));
#pragma unroll
                for (int i = 0; i < 2; i++)
#pragma unroll
                    for (int j = 0; j < 4; j++) {
                        int jj = j >> 1, s = (j & 1) * 2;
                        mma_bf16(acc[i][j], ah[i], bh[jj][s], bh[jj][s + 1]);
                    }
            }
        }

        const int m0rel = m0 - mstart;
#pragma unroll
        for (int i = 0; i < 2; i++)
#pragma unroll
            for (int r = 0; r < 2; r++) {
                float xsi = xs[i][r], cc = cA[i][r];
#pragma unroll
                for (int j = 0; j < 4; j++) {
                    int ml = warp_m * 32 + j * 8 + 2 * tg;
                    int mA = m0 + ml;
                    float dA = acc[i][j][r * 2 + 0];
                    float dB = acc[i][j][r * 2 + 1];
                    float d2A = fmaxf(fmaf(-2.f, dA, xsi + tYS[ml]), 0.f);
                    float d2B = fmaxf(fmaf(-2.f, dB, xsi + tYS[ml + 1]), 0.f);
                    float tA = d2A * cc * tRY[ml];
                    float tB = d2B * cc * tRY[ml + 1];
                    uint32_t pkA = (__float_as_uint(tA) & 0xFFFFF800u)
                                   | (uint32_t)(m0rel + ml);
                    uint32_t pkB = (__float_as_uint(tB) & 0xFFFFF800u)
                                   | (uint32_t)(m0rel + ml + 1);
                    if (mA < mend && pkA < lw[i][r]) ins4u(la[i][r], lw[i][r], pkA);
                    if (mA + 1 < mend && pkB < lw[i][r]) ins4u(la[i][r], lw[i][r], pkB);
                }
            }
    }

#pragma unroll
    for (int i = 0; i < 2; i++)
#pragma unroll
        for (int r = 0; r < 2; r++) {
            int q = q0 + warp_q * 32 + i * 16 + r * 8 + g4;
            int base = (q * NSPLIT + blockIdx.y) * CPS + (warp_m * 4 + tg) * 4;
#pragma unroll
            for (int l = 0; l < 4; l++)
                g_cand[base + l] = la[i][r][l];
        }
}

// ============================================================
// Kernel 3: per-warp top-8 (u32) -> warp-parallel union 8th -> threshold ->
// refine list -> EXACT fp32 rerank -> softmax -> gather. (UNCHANGED)
// ============================================================
__device__ __forceinline__ float dec_t(uint32_t v) {
    return __uint_as_float(v & 0xFFFFF800u);
}

__global__ void merge_kernel(const float* __restrict__ masks, float* __restrict__ out)
{
    __shared__ uint32_t cv[NC2];
    __shared__ uint32_t w8[8][8];
    __shared__ float qf[DD];
    __shared__ int   ridx[RCAP];
    __shared__ float ra[RCAP];
    __shared__ float sel_a[KSEL];
    __shared__ int   sel_i[KSEL];
    __shared__ float s_thresh;
    __shared__ int   scnt;

    const int q = blockIdx.x;
    const int tid = threadIdx.x;
    const int lane = tid & 31, wid = tid >> 5;

    if (tid == 0) scnt = 0;
    for (int c = tid; c < NC2; c += 256) cv[c] = g_cand[q * NC2 + c];
    if (tid < 128) {
        unsigned h = g_q_hi[q * 128 + tid];
        unsigned l = g_q_lo[q * 128 + tid];
        qf[2 * tid + 0] = bflo(h) + bflo(l);
        qf[2 * tid + 1] = bfhi(h) + bfhi(l);
    }
    __syncthreads();

    // ---- per-warp top-8 over its 148 candidates ----
    {
        const int wbase = wid * 148;
        uint32_t v[5];
#pragma unroll
        for (int k = 0; k < 5; k++) {
            int c = wbase + lane + 32 * k;
            v[k] = (lane + 32 * k < 148) ? cv[c] : 0xFFFFFFFFu;
        }
#pragma unroll
        for (int r = 0; r < 8; r++) {
            uint32_t lmin = v[0]; int pos = 0;
#pragma unroll
            for (int k = 1; k < 5; k++)
                if (v[k] < lmin) { lmin = v[k]; pos = k; }
            uint32_t rmin = lmin;
#pragma unroll
            for (int off = 16; off; off >>= 1)
                rmin = min(rmin, __shfl_xor_sync(0xffffffffu, rmin, off));
            unsigned ball = __ballot_sync(0xffffffffu, lmin == rmin);
            if (lane == (int)(__ffs(ball) - 1)) v[pos] = 0xFFFFFFFFu;
            if (lane == 0) w8[wid][r] = rmin;
        }
    }
    __syncthreads();

    // ---- warp-parallel 8th smallest of the 64-entry union ----
    if (wid == 0) {
        uint32_t v0 = ((uint32_t*)w8)[lane];
        uint32_t v1 = ((uint32_t*)w8)[lane + 32];
        uint32_t e8 = 0;
#pragma unroll
        for (int r = 0; r < 8; r++) {
            uint32_t lm = min(v0, v1);
            uint32_t rm = lm;
#pragma unroll
            for (int off = 16; off; off >>= 1)
                rm = min(rm, __shfl_xor_sync(0xffffffffu, rm, off));
            e8 = rm;
            unsigned ball = __ballot_sync(0xffffffffu, lm == rm);
            if (lane == (int)(__ffs(ball) - 1)) {
                if (v0 == rm) v0 = 0xFFFFFFFFu; else v1 = 0xFFFFFFFFu;
            }
        }
        if (lane == 0) s_thresh = 1.0f + dec_t(e8) + MARGIN;
    }
    __syncthreads();

    // ---- refine list ----
    const float thresh = s_thresh;
    for (int c = tid; c < NC2; c += 256) {
        uint32_t pv = cv[c];
        float t = dec_t(pv);
        if (1.0f + t <= thresh) {
            int idx = (c >> 5) * SPLEN + (int)(pv & 0x7FFu);
            if (idx < NM) {
                int p = atomicAdd(&scnt, 1);
                if (p < RCAP) ridx[p] = idx;
            }
        }
    }
    __syncthreads();
    const int cnt = min(scnt, RCAP);
    const float x_sq = g_q_sq[q];
    const float invx = 1.0f - x_sq;

    // ---- exact fp32 dots (warp per candidate) ----
    for (int c = wid; c < cnt; c += 8) {
        int m = ridx[c];
        const uint4* ph = (const uint4*)(g_mem_hi + (size_t)m * 128);
        const uint4* pl = (const uint4*)(g_mem_lo + (size_t)m * 128);
        uint4 h = ph[lane], l = pl[lane];
        const float* qp = &qf[lane * 8];
        float dot;
        dot  = (bflo(h.x) + bflo(l.x)) * qp[0];
        dot += (bfhi(h.x) + bfhi(l.x)) * qp[1];
        dot += (bflo(h.y) + bflo(l.y)) * qp[2];
        dot += (bfhi(h.y) + bfhi(l.y)) * qp[3];
        dot += (bflo(h.z) + bflo(l.z)) * qp[4];
        dot += (bfhi(h.z) + bfhi(l.z)) * qp[5];
        dot += (bflo(h.w) + bflo(l.w)) * qp[6];
        dot += (bfhi(h.w) + bfhi(l.w)) * qp[7];
#pragma unroll
        for (int off = 16; off; off >>= 1)
            dot += __shfl_xor_sync(0xffffffffu, dot, off);
        if (lane == 0) {
            float ysq = g_mem_sq[m];
            float d2 = fmaxf(x_sq + ysq - 2.f * dot, 0.f);
            float arg = 1.f + 2.f * d2 / (invx * (1.f - ysq) + 1e-8f);
            ra[c] = fmaxf(arg, 1.0f + 1e-6f);
        }
    }
    __syncthreads();

    // ---- final exact top-8 (warp 0), lexicographic (arg, idx) ----
    if (wid == 0) {
        for (int r = 0; r < KSEL; r++) {
            float ba = BIGF; int bi = 0x7fffffff, bp = 0;
            for (int c = lane; c < cnt; c += 32) {
                float a = ra[c]; int i = ridx[c];
                if (a < ba || (a == ba && i < bi)) { ba = a; bi = i; bp = c; }
            }
#pragma unroll
            for (int off = 16; off; off >>= 1) {
                float oa = __shfl_down_sync(0xffffffffu, ba, off);
                int oi = __shfl_down_sync(0xffffffffu, bi, off);
                int op = __shfl_down_sync(0xffffffffu, bp, off);
                if (oa < ba || (oa == ba && oi < bi)) { ba = oa; bi = oi; bp = op; }
            }
            ba = __shfl_sync(0xffffffffu, ba, 0);
            bi = __shfl_sync(0xffffffffu, bi, 0);
            bp = __shfl_sync(0xffffffffu, bp, 0);
            if (lane == 0) {
                sel_a[r] = ba; sel_i[r] = bi;
                ra[bp] = BIGF;
            }
            __syncwarp();
        }
    }
    __syncthreads();

    if (tid == 0) {
        float d[KSEL];
#pragma unroll
        for (int s = 0; s < KSEL; s++) d[s] = acoshf(sel_a[s]);
        float d0 = d[0];
        float e[KSEL], sum = 0.f;
#pragma unroll
        for (int s = 0; s < KSEL; s++) { e[s] = expf(d0 - d[s]); sum += e[s]; }
        float inv = 1.0f / sum;
#pragma unroll
        for (int s = 0; s < KSEL; s++) out[q * KSEL + s] = e[s] * inv;
    }
    __syncthreads();

    float4* hout = (float4*)(out + (size_t)BQ * KSEL);
    for (int e = tid; e < KSEL * (MAXA / 4); e += 256) {
        int s = e / (MAXA / 4), a4 = e - s * (MAXA / 4);
        const float4* src = (const float4*)(masks + (size_t)sel_i[s] * MAXA);
        hout[((size_t)q * KSEL + s) * (MAXA / 4) + a4] = src[a4];
    }
}

// ============================================================
extern "C" void kernel_launch(void* const* d_in, const int* in_sizes, int n_in,
                              void* d_out, int out_size)
{
    (void)in_sizes; (void)n_in; (void)out_size;
    const float* q_emb  = (const float*)d_in[0];
    const float* m_emb  = (const float*)d_in[1];
    const float* masks  = (const float*)d_in[2];
    const float* W      = (const float*)d_in[3];
    const float* bias   = (const float*)d_in[4];
    float* out = (float*)d_out;

    unsigned *d_mhi, *d_mlo, *d_qhi, *d_qlo;
    float *d_msq, *d_qsq, *d_hm, *d_hq, *d_xpm, *d_xpq;
    cudaGetSymbolAddress((void**)&d_mhi, g_mem_hi);
    cudaGetSymbolAddress((void**)&d_mlo, g_mem_lo);
    cudaGetSymbolAddress((void**)&d_qhi, g_q_hi);
    cudaGetSymbolAddress((void**)&d_qlo, g_q_lo);
    cudaGetSymbolAddress((void**)&d_msq, g_mem_sq);
    cudaGetSymbolAddress((void**)&d_qsq, g_q_sq);
    cudaGetSymbolAddress((void**)&d_hm,  g_h_mem);
    cudaGetSymbolAddress((void**)&d_hq,  g_h_q);
    cudaGetSymbolAddress((void**)&d_xpm, g_xp_mem);
    cudaGetSymbolAddress((void**)&d_xpq, g_xp_q);

    cudaFuncSetAttribute(dist_topk_kernel,
                         cudaFuncAttributeMaxDynamicSharedMemorySize, DSMEM_SZ);
    cudaFuncSetAttribute(gemm_tanh_kernel,
                         cudaFuncAttributeMaxDynamicSharedMemorySize, GSM_BYTES);

    // one-time tf32 hi/lo presplit
    presplit_x_kernel<<<(NM * 64 + 255) / 256, 256>>>(m_emb, d_xpm, NM);
    presplit_x_kernel<<<(BQ * 64 + 255) / 256, 256>>>(q_emb, d_xpq, BQ);
    presplit_w_kernel<<<(256 * 64 + 255) / 256, 256>>>(W);

    // tf32 3-term GEMM + tanh (cp.async double-buffered)
    dim3 gm((NM + 127) / 128, 4), gq((BQ + 127) / 128, 4);
    gemm_tanh_kernel<<<gm, 256, GSM_BYTES>>>(d_xpm, bias, d_hm, NM);
    gemm_tanh_kernel<<<gq, 256, GSM_BYTES>>>(d_xpq, bias, d_hq, BQ);

    // Poincare rescale + |h|^2 + bf16 hi/lo split (stride-128 FIXED)
    norm_split_kernel<<<(NM + 7) / 8, 256>>>(d_hm, d_mhi, d_mlo, d_msq, NM);
    norm_split_kernel<<<(BQ + 7) / 8, 256>>>(d_hq, d_qhi, d_qlo, d_qsq, BQ);

    dim3 g2(BQ / 128, NSPLIT);
    dist_topk_kernel<<<g2, 256, DSMEM_SZ>>>();

    merge_kernel<<<BQ, 256>>>(masks, out);
}

// round 17
// speedup vs baseline: 1.1851x; 1.1851x over previous
#include <cuda_runtime.h>
#include <cuda_bf16.h>
#include <math.h>
#include <stdint.h>

#define BQ    1024
#define NM    50000
#define DD    256
#define MAXA  200
#define KSEL  8
#define NSPLIT 37
#define SPLEN  1352            // ceil(50000/37)
#define CPS   32               // candidates per (query, split): 8 threads x top-4
#define NC2   (NSPLIT*CPS)     // 1184 candidates per query at merge
#define RCAP  64               // refine-list capacity
#define MARGIN 4.25f           // approx err (~1.5) *2 + quantization slack
#define BIGF  3.0e38f

// -------- device scratch --------
__device__ unsigned g_mem_hi[NM * 128];   // bf16x2: col pair per u32
__device__ unsigned g_mem_lo[NM * 128];
__device__ unsigned g_q_hi[BQ * 128];
__device__ unsigned g_q_lo[BQ * 128];
__device__ float    g_mem_sq[NM];
__device__ float    g_q_sq[BQ];
__device__ uint32_t g_cand[BQ * NC2];     // packed: arg-bits[31:11] | m_rel[10:0]
__device__ float    g_h_mem[NM * 256];    // tanh(xW+b) fp32
__device__ float    g_h_q[BQ * 256];
__device__ float    g_wp[256 * 512];      // W^T, tf32 hi/lo pairs, k-permuted

// ===================== PTX helpers =====================
__device__ __forceinline__ uint32_t smem_u32(const void* p) {
    uint32_t a;
    asm("{ .reg .u64 t; cvta.to.shared.u64 t, %1; cvt.u32.u64 %0, t; }" : "=r"(a) : "l"(p));
    return a;
}
#define LDSM_X4(r0, r1, r2, r3, addr) \
    asm volatile("ldmatrix.sync.aligned.m8n8.x4.shared.b16 {%0,%1,%2,%3}, [%4];" \
        : "=r"(r0), "=r"(r1), "=r"(r2), "=r"(r3) : "r"(addr))

__device__ __forceinline__ void mma_bf16(float* c, const uint32_t* a,
                                         uint32_t b0, uint32_t b1) {
    asm volatile("mma.sync.aligned.m16n8k16.row.col.f32.bf16.bf16.f32 "
        "{%0,%1,%2,%3},{%4,%5,%6,%7},{%8,%9},{%0,%1,%2,%3};"
        : "+f"(c[0]), "+f"(c[1]), "+f"(c[2]), "+f"(c[3])
        : "r"(a[0]), "r"(a[1]), "r"(a[2]), "r"(a[3]), "r"(b0), "r"(b1));
}
__device__ __forceinline__ void mma_tf32(float* c,
                                         uint32_t a0, uint32_t a1, uint32_t a2, uint32_t a3,
                                         uint32_t b0, uint32_t b1) {
    asm volatile("mma.sync.aligned.m16n8k8.row.col.f32.tf32.tf32.f32 "
        "{%0,%1,%2,%3},{%4,%5,%6,%7},{%8,%9},{%0,%1,%2,%3};"
        : "+f"(c[0]), "+f"(c[1]), "+f"(c[2]), "+f"(c[3])
        : "r"(a0), "r"(a1), "r"(a2), "r"(a3), "r"(b0), "r"(b1));
}
__device__ __forceinline__ float tf32f(float x) {
    uint32_t u;
    asm("cvt.rna.tf32.f32 %0, %1;" : "=r"(u) : "f"(x));
    return __uint_as_float(u);
}

// bf16x2 unpack: even dim in low 16 bits, odd dim in high 16 bits
__device__ __forceinline__ float bflo(uint32_t v) { return __uint_as_float(v << 16); }
__device__ __forceinline__ float bfhi(uint32_t v) { return __uint_as_float(v & 0xffff0000u); }

// ============================================================
// Presplit W: fp32 -> tf32 (hi,lo) pairs, k-permuted pair layout
// (pair_pos(kk) == s*16 + half*2 + e*4, identical to in-kernel layout).
// ============================================================
__device__ __forceinline__ int pair_pos(int kk) {   // kk = k & 15
    return ((kk >> 3) << 4) + (((kk >> 2) & 1) << 1) + ((kk & 3) << 2);
}

__global__ void presplit_w_kernel(const float* __restrict__ W)
{
    int idx = blockIdx.x * blockDim.x + threadIdx.x;   // one per 4 consecutive cols
    if (idx >= 256 * 64) return;
    int k = idx >> 6;
    int c4 = (idx & 63) * 4;
    float4 v = *(const float4*)&W[k * 256 + c4];
    float vv[4] = {v.x, v.y, v.z, v.w};
    int pp = (k >> 4) * 32 + pair_pos(k & 15);
#pragma unroll
    for (int e = 0; e < 4; e++) {
        float hi = tf32f(vv[e]);
        float lo = tf32f(vv[e] - hi);
        *(float2*)&g_wp[(c4 + e) * 512 + pp] = make_float2(hi, lo);
    }
}

// ============================================================
// Kernel 1a: tf32 4-term split GEMM + tanh (R14 structure).
// X: in-kernel hi/lo split (DRAM-cheap). W: presplit coalesced copies.
// Grid (4 col-blocks FASTEST, 391 row-blocks) -> X reads L2-coalesced.
// ============================================================
union GemmSmem {
    struct { float QS[128 * 36]; float WS[64 * 36]; } t;
    float HS[128 * 68];
};

__global__ __launch_bounds__(256, 2)
void gemm_tanh_kernel(const float* __restrict__ X, const float* __restrict__ bias,
                      float* __restrict__ H, int M)
{
    __shared__ __align__(16) GemmSmem gs;
    __shared__ float sbias[64];

    const int tid = threadIdx.x;
    const int lane = tid & 31;
    const int wid = tid >> 5;
    const int warp_q = wid & 3;
    const int warp_m = wid >> 2;
    const int g4 = lane >> 2;
    const int tg = lane & 3;

    const int q0 = blockIdx.y * 128;
    const int c0 = blockIdx.x * 64;

    if (tid < 64) sbias[tid] = bias[c0 + tid];

    float acc[2][4][4];
#pragma unroll
    for (int i = 0; i < 2; i++)
#pragma unroll
        for (int j = 0; j < 4; j++)
#pragma unroll
            for (int c = 0; c < 4; c++) acc[i][j][c] = 0.f;

    for (int kc = 0; kc < DD; kc += 16) {
        // ---- QS fill: 128 rows x 16 k, in-kernel tf32 hi/lo split ----
#pragma unroll
        for (int it = 0; it < 2; it++) {
            int idx = tid + 256 * it;            // 512 float4
            int q = idx >> 2;
            int k4 = (idx & 3) * 4;
            float4 v = make_float4(0.f, 0.f, 0.f, 0.f);
            if (q0 + q < M)
                v = *(const float4*)&X[(size_t)(q0 + q) * DD + kc + k4];
            int s = k4 >> 3, half = (k4 >> 2) & 1;
            int ob = s * 16 + half * 2;
            float vv[4] = {v.x, v.y, v.z, v.w};
#pragma unroll
            for (int e = 0; e < 4; e++) {
                float hi = tf32f(vv[e]);
                float lo = tf32f(vv[e] - hi);
                gs.t.QS[q * 36 + ob + e * 4 + 0] = hi;
                gs.t.QS[q * 36 + ob + e * 4 + 1] = lo;
            }
        }
        // ---- WS fill: presplit, coalesced float4 copies (512 float4 / 2 its) ----
        {
            int r = tid >> 2;                    // column within block (0..63)
            int f4 = (tid & 3);                  // 4 float4 per row half... need 8
#pragma unroll
            for (int h = 0; h < 2; h++) {
                int ff = f4 * 2 + h;             // 0..7
                float4 v = *(const float4*)&g_wp[(size_t)(c0 + r) * 512
                                                 + (kc >> 4) * 32 + ff * 4];
                *(float4*)&gs.t.WS[r * 36 + ff * 4] = v;
            }
        }
        __syncthreads();

#pragma unroll
        for (int s = 0; s < 2; s++) {
            const int off = s * 16 + tg * 4;
            uint32_t ah[2][4], al[2][4];
#pragma unroll
            for (int i = 0; i < 2; i++) {
                int qr = warp_q * 32 + i * 16 + g4;
                float4 p0 = *(const float4*)&gs.t.QS[qr * 36 + off];
                float4 p1 = *(const float4*)&gs.t.QS[(qr + 8) * 36 + off];
                ah[i][0] = __float_as_uint(p0.x); al[i][0] = __float_as_uint(p0.y);
                ah[i][2] = __float_as_uint(p0.z); al[i][2] = __float_as_uint(p0.w);
                ah[i][1] = __float_as_uint(p1.x); al[i][1] = __float_as_uint(p1.y);
                ah[i][3] = __float_as_uint(p1.z); al[i][3] = __float_as_uint(p1.w);
            }
            uint32_t bh[4][2], bl[4][2];
#pragma unroll
            for (int j = 0; j < 4; j++) {
                int mr = warp_m * 32 + j * 8 + g4;
                float4 p = *(const float4*)&gs.t.WS[mr * 36 + off];
                bh[j][0] = __float_as_uint(p.x); bl[j][0] = __float_as_uint(p.y);
                bh[j][1] = __float_as_uint(p.z); bl[j][1] = __float_as_uint(p.w);
            }
#pragma unroll
            for (int i = 0; i < 2; i++)
#pragma unroll
                for (int j = 0; j < 4; j++) {
                    mma_tf32(acc[i][j], ah[i][0], ah[i][1], ah[i][2], ah[i][3],
                             bh[j][0], bh[j][1]);
                    mma_tf32(acc[i][j], ah[i][0], ah[i][1], ah[i][2], ah[i][3],
                             bl[j][0], bl[j][1]);
                    mma_tf32(acc[i][j], al[i][0], al[i][1], al[i][2], al[i][3],
                             bh[j][0], bh[j][1]);
                    mma_tf32(acc[i][j], al[i][0], al[i][1], al[i][2], al[i][3],
                             bl[j][0], bl[j][1]);
                }
        }
        __syncthreads();
    }

    // epilogue: bias + tanh -> smem stage -> coalesced global write
#pragma unroll
    for (int i = 0; i < 2; i++)
#pragma unroll
        for (int r = 0; r < 2; r++) {
            int q = warp_q * 32 + i * 16 + r * 8 + g4;
#pragma unroll
            for (int j = 0; j < 4; j++) {
                int ml = warp_m * 32 + j * 8 + 2 * tg;
                float vA = tanhf(acc[i][j][r * 2 + 0] + sbias[ml]);
                float vB = tanhf(acc[i][j][r * 2 + 1] + sbias[ml + 1]);
                *(float2*)&gs.HS[q * 68 + ml] = make_float2(vA, vB);
            }
        }
    __syncthreads();

#pragma unroll
    for (int it = 0; it < 8; it++) {
        int idx = tid + 256 * it;
        int row = idx >> 4, f4 = idx & 15;
        if (q0 + row < M)
            *(float4*)&H[(size_t)(q0 + row) * DD + c0 + f4 * 4] =
                *(const float4*)&gs.HS[row * 68 + f4 * 4];
    }
}

// ============================================================
// Kernel 1b: Norm/rescale/split (row stride 128 — FIXED, R14).
// ============================================================
__global__ void norm_split_kernel(const float* __restrict__ H,
                                  unsigned* __restrict__ Hhi, unsigned* __restrict__ Hlo,
                                  float* __restrict__ SQ, int M)
{
    const int lane = threadIdx.x & 31;
    const int wid = threadIdx.x >> 5;
    const int row = blockIdx.x * 8 + wid;
    if (row >= M) return;

    float4 a = *(const float4*)&H[(size_t)row * 256 + lane * 8];
    float4 b = *(const float4*)&H[(size_t)row * 256 + lane * 8 + 4];
    float ss = a.x * a.x + a.y * a.y + a.z * a.z + a.w * a.w
             + b.x * b.x + b.y * b.y + b.z * b.z + b.w * b.w;
#pragma unroll
    for (int off = 16; off; off >>= 1)
        ss += __shfl_xor_sync(0xffffffffu, ss, off);

    float norm = sqrtf(ss);
    float sc = (norm > 0.95f) ? 0.95f / norm : 1.0f;
    if (lane == 0) SQ[row] = ss * sc * sc;

    float v[8] = {a.x * sc, a.y * sc, a.z * sc, a.w * sc,
                  b.x * sc, b.y * sc, b.z * sc, b.w * sc};
    uint32_t hiw[4], low[4];
#pragma unroll
    for (int p = 0; p < 4; p++) {
        float vx = v[2 * p], vy = v[2 * p + 1];
        __nv_bfloat16 hx = __float2bfloat16(vx);
        __nv_bfloat16 hy = __float2bfloat16(vy);
        __nv_bfloat16 lx = __float2bfloat16(vx - __bfloat162float(hx));
        __nv_bfloat16 ly = __float2bfloat16(vy - __bfloat162float(hy));
        hiw[p] = ((unsigned)__bfloat16_as_ushort(hy) << 16) | __bfloat16_as_ushort(hx);
        low[p] = ((unsigned)__bfloat16_as_ushort(ly) << 16) | __bfloat16_as_ushort(lx);
    }
    *(uint4*)&Hhi[(size_t)row * 128 + lane * 4] = make_uint4(hiw[0], hiw[1], hiw[2], hiw[3]);
    *(uint4*)&Hlo[(size_t)row * 128 + lane * 4] = make_uint4(low[0], low[1], low[2], low[3]);
}

// ============================================================
// Kernel 2: bf16 hi-only mma pruning pass (R14 version — sync fills).
// ============================================================
#define RS       144
#define QCH_B    (128 * RS)
#define MCH_B    (64 * RS)
#define OFF_Q    0
#define OFF_M    (4 * QCH_B)
#define OFF_YS   (OFF_M + 4 * MCH_B)
#define OFF_RY   (OFF_YS + 256)
#define DSMEM_SZ (OFF_RY + 256)

__device__ __forceinline__ void ins4u(uint32_t (&la)[4], uint32_t& worst, uint32_t pk) {
    int mp = 0; uint32_t mv = la[0];
    if (la[1] > mv) { mv = la[1]; mp = 1; }
    if (la[2] > mv) { mv = la[2]; mp = 2; }
    if (la[3] > mv) { mv = la[3]; mp = 3; }
    la[mp] = pk;
    mv = la[0];
    if (la[1] > mv) mv = la[1];
    if (la[2] > mv) mv = la[2];
    if (la[3] > mv) mv = la[3];
    worst = mv;
}

__global__ __launch_bounds__(256, 2)
void dist_topk_kernel()
{
    extern __shared__ char sb[];
    const uint32_t sbase = smem_u32(sb);
    float* tYS = (float*)(sb + OFF_YS);
    float* tRY = (float*)(sb + OFF_RY);

    const int tid = threadIdx.x;
    const int lane = tid & 31;
    const int wid = tid >> 5;
    const int warp_q = wid & 3;
    const int warp_m = wid >> 2;
    const int g4 = lane >> 2;
    const int tg = lane & 3;

    const int q0 = blockIdx.x * 128;
    const int mstart = blockIdx.y * SPLEN;
    const int mend = min(mstart + SPLEN, NM);

    const uint32_t aOff = (uint32_t)((warp_q * 32 + (lane & 7) + ((lane >> 3) & 1) * 8) * RS
                                     + (((lane >> 4) & 1) * 8) * 2);
    const uint32_t bOff = (uint32_t)((warp_m * 32 + (lane & 7) + ((lane >> 4) & 1) * 8) * RS
                                     + (((lane >> 3) & 1) * 8) * 2);
    const uint32_t u_q = sbase + OFF_Q;
    const uint32_t u_m = sbase + OFF_M;

    float xs[2][2], cA[2][2];
#pragma unroll
    for (int i = 0; i < 2; i++)
#pragma unroll
        for (int r = 0; r < 2; r++) {
            float v = g_q_sq[q0 + warp_q * 32 + i * 16 + r * 8 + g4];
            xs[i][r] = v;
            cA[i][r] = 2.0f / (1.0f - v);
        }

    uint32_t la[2][2][4];
    uint32_t lw[2][2];
#pragma unroll
    for (int i = 0; i < 2; i++)
#pragma unroll
        for (int r = 0; r < 2; r++) {
            lw[i][r] = 0xFFFFFFFFu;
#pragma unroll
            for (int l = 0; l < 4; l++) la[i][r][l] = 0xFFFFFFFFu;
        }

    {
        const uint4* pQH = (const uint4*)g_q_hi;
#pragma unroll
        for (int it = 0; it < 16; it++) {
            int idx = tid + 256 * it;
            int r = idx >> 5, u = idx & 31;
            int chunk = u >> 3, kb = u & 7;
            uint4 v = pQH[(size_t)(q0 + r) * 32 + u];
            *(uint4*)(sb + OFF_Q + chunk * QCH_B + r * RS + kb * 16) = v;
        }
    }

    const uint4* pMH = (const uint4*)g_mem_hi;

    for (int m0 = mstart; m0 < mend; m0 += 64) {
        __syncthreads();

        if (tid < 64) {
            int m = m0 + tid;
            float ys = (m < mend) ? g_mem_sq[m] : 0.f;
            tYS[tid] = ys;
            tRY[tid] = __frcp_rn(1.0f - ys);
        }
#pragma unroll
        for (int it = 0; it < 8; it++) {
            int idx = tid + 256 * it;
            int r = idx >> 5, u = idx & 31;
            int chunk = u >> 3, kb = u & 7;
            uint4 v = make_uint4(0u, 0u, 0u, 0u);
            if (m0 + r < mend) v = pMH[(size_t)(m0 + r) * 32 + u];
            *(uint4*)(sb + OFF_M + chunk * MCH_B + r * RS + kb * 16) = v;
        }
        __syncthreads();

        float acc[2][4][4];
#pragma unroll
        for (int i = 0; i < 2; i++)
#pragma unroll
            for (int j = 0; j < 4; j++)
#pragma unroll
                for (int c = 0; c < 4; c++) acc[i][j][c] = 0.f;

#pragma unroll
        for (int c = 0; c < 4; c++) {
            const uint32_t aBase = u_q + c * QCH_B + aOff;
            const uint32_t bBase = u_m + c * MCH_B + bOff;
#pragma unroll
            for (int ks = 0; ks < 4; ks++) {
                uint32_t ah[2][4], bh[2][4];
#pragma unroll
                for (int i = 0; i < 2; i++)
                    LDSM_X4(ah[i][0], ah[i][1], ah[i][2], ah[i][3],
                            aBase + ks * 32 + i * (16 * RS));
#pragma unroll
                for (int jj = 0; jj < 2; jj++)
                    LDSM_X4(bh[jj][0], bh[jj][1], bh[jj][2], bh[jj][3],
                            bBase + ks * 32 + jj * (16 * RS));
#pragma unroll
                for (int i = 0; i < 2; i++)
#pragma unroll
                    for (int j = 0; j < 4; j++) {
                        int jj = j >> 1, s = (j & 1) * 2;
                        mma_bf16(acc[i][j], ah[i], bh[jj][s], bh[jj][s + 1]);
                    }
            }
        }

        const int m0rel = m0 - mstart;
#pragma unroll
        for (int i = 0; i < 2; i++)
#pragma unroll
            for (int r = 0; r < 2; r++) {
                float xsi = xs[i][r], cc = cA[i][r];
#pragma unroll
                for (int j = 0; j < 4; j++) {
                    int ml = warp_m * 32 + j * 8 + 2 * tg;
                    int mA = m0 + ml;
                    float dA = acc[i][j][r * 2 + 0];
                    float dB = acc[i][j][r * 2 + 1];
                    float d2A = fmaxf(fmaf(-2.f, dA, xsi + tYS[ml]), 0.f);
                    float d2B = fmaxf(fmaf(-2.f, dB, xsi + tYS[ml + 1]), 0.f);
                    float tA = d2A * cc * tRY[ml];
                    float tB = d2B * cc * tRY[ml + 1];
                    uint32_t pkA = (__float_as_uint(tA) & 0xFFFFF800u)
                                   | (uint32_t)(m0rel + ml);
                    uint32_t pkB = (__float_as_uint(tB) & 0xFFFFF800u)
                                   | (uint32_t)(m0rel + ml + 1);
                    if (mA < mend && pkA < lw[i][r]) ins4u(la[i][r], lw[i][r], pkA);
                    if (mA + 1 < mend && pkB < lw[i][r]) ins4u(la[i][r], lw[i][r], pkB);
                }
            }
    }

#pragma unroll
    for (int i = 0; i < 2; i++)
#pragma unroll
        for (int r = 0; r < 2; r++) {
            int q = q0 + warp_q * 32 + i * 16 + r * 8 + g4;
            int base = (q * NSPLIT + blockIdx.y) * CPS + (warp_m * 4 + tg) * 4;
#pragma unroll
            for (int l = 0; l < 4; l++)
                g_cand[base + l] = la[i][r][l];
        }
}

// ============================================================
// Kernel 3: merge (R14 version — warp-parallel union).
// ============================================================
__device__ __forceinline__ float dec_t(uint32_t v) {
    return __uint_as_float(v & 0xFFFFF800u);
}

__global__ void merge_kernel(const float* __restrict__ masks, float* __restrict__ out)
{
    __shared__ uint32_t cv[NC2];
    __shared__ uint32_t w8[8][8];
    __shared__ float qf[DD];
    __shared__ int   ridx[RCAP];
    __shared__ float ra[RCAP];
    __shared__ float sel_a[KSEL];
    __shared__ int   sel_i[KSEL];
    __shared__ float s_thresh;
    __shared__ int   scnt;

    const int q = blockIdx.x;
    const int tid = threadIdx.x;
    const int lane = tid & 31, wid = tid >> 5;

    if (tid == 0) scnt = 0;
    for (int c = tid; c < NC2; c += 256) cv[c] = g_cand[q * NC2 + c];
    if (tid < 128) {
        unsigned h = g_q_hi[q * 128 + tid];
        unsigned l = g_q_lo[q * 128 + tid];
        qf[2 * tid + 0] = bflo(h) + bflo(l);
        qf[2 * tid + 1] = bfhi(h) + bfhi(l);
    }
    __syncthreads();

    {
        const int wbase = wid * 148;
        uint32_t v[5];
#pragma unroll
        for (int k = 0; k < 5; k++) {
            int c = wbase + lane + 32 * k;
            v[k] = (lane + 32 * k < 148) ? cv[c] : 0xFFFFFFFFu;
        }
#pragma unroll
        for (int r = 0; r < 8; r++) {
            uint32_t lmin = v[0]; int pos = 0;
#pragma unroll
            for (int k = 1; k < 5; k++)
                if (v[k] < lmin) { lmin = v[k]; pos = k; }
            uint32_t rmin = lmin;
#pragma unroll
            for (int off = 16; off; off >>= 1)
                rmin = min(rmin, __shfl_xor_sync(0xffffffffu, rmin, off));
            unsigned ball = __ballot_sync(0xffffffffu, lmin == rmin);
            if (lane == (int)(__ffs(ball) - 1)) v[pos] = 0xFFFFFFFFu;
            if (lane == 0) w8[wid][r] = rmin;
        }
    }
    __syncthreads();

    if (wid == 0) {
        uint32_t v0 = ((uint32_t*)w8)[lane];
        uint32_t v1 = ((uint32_t*)w8)[lane + 32];
        uint32_t e8 = 0;
#pragma unroll
        for (int r = 0; r < 8; r++) {
            uint32_t lm = min(v0, v1);
            uint32_t rm = lm;
#pragma unroll
            for (int off = 16; off; off >>= 1)
                rm = min(rm, __shfl_xor_sync(0xffffffffu, rm, off));
            e8 = rm;
            unsigned ball = __ballot_sync(0xffffffffu, lm == rm);
            if (lane == (int)(__ffs(ball) - 1)) {
                if (v0 == rm) v0 = 0xFFFFFFFFu; else v1 = 0xFFFFFFFFu;
            }
        }
        if (lane == 0) s_thresh = 1.0f + dec_t(e8) + MARGIN;
    }
    __syncthreads();

    const float thresh = s_thresh;
    for (int c = tid; c < NC2; c += 256) {
        uint32_t pv = cv[c];
        float t = dec_t(pv);
        if (1.0f + t <= thresh) {
            int idx = (c >> 5) * SPLEN + (int)(pv & 0x7FFu);
            if (idx < NM) {
                int p = atomicAdd(&scnt, 1);
                if (p < RCAP) ridx[p] = idx;
            }
        }
    }
    __syncthreads();
    const int cnt = min(scnt, RCAP);
    const float x_sq = g_q_sq[q];
    const float invx = 1.0f - x_sq;

    for (int c = wid; c < cnt; c += 8) {
        int m = ridx[c];
        const uint4* ph = (const uint4*)(g_mem_hi + (size_t)m * 128);
        const uint4* pl = (const uint4*)(g_mem_lo + (size_t)m * 128);
        uint4 h = ph[lane], l = pl[lane];
        const float* qp = &qf[lane * 8];
        float dot;
        dot  = (bflo(h.x) + bflo(l.x)) * qp[0];
        dot += (bfhi(h.x) + bfhi(l.x)) * qp[1];
        dot += (bflo(h.y) + bflo(l.y)) * qp[2];
        dot += (bfhi(h.y) + bfhi(l.y)) * qp[3];
        dot += (bflo(h.z) + bflo(l.z)) * qp[4];
        dot += (bfhi(h.z) + bfhi(l.z)) * qp[5];
        dot += (bflo(h.w) + bflo(l.w)) * qp[6];
        dot += (bfhi(h.w) + bfhi(l.w)) * qp[7];
#pragma unroll
        for (int off = 16; off; off >>= 1)
            dot += __shfl_xor_sync(0xffffffffu, dot, off);
        if (lane == 0) {
            float ysq = g_mem_sq[m];
            float d2 = fmaxf(x_sq + ysq - 2.f * dot, 0.f);
            float arg = 1.f + 2.f * d2 / (invx * (1.f - ysq) + 1e-8f);
            ra[c] = fmaxf(arg, 1.0f + 1e-6f);
        }
    }
    __syncthreads();

    if (wid == 0) {
        for (int r = 0; r < KSEL; r++) {
            float ba = BIGF; int bi = 0x7fffffff, bp = 0;
            for (int c = lane; c < cnt; c += 32) {
                float a = ra[c]; int i = ridx[c];
                if (a < ba || (a == ba && i < bi)) { ba = a; bi = i; bp = c; }
            }
#pragma unroll
            for (int off = 16; off; off >>= 1) {
                float oa = __shfl_down_sync(0xffffffffu, ba, off);
                int oi = __shfl_down_sync(0xffffffffu, bi, off);
                int op = __shfl_down_sync(0xffffffffu, bp, off);
                if (oa < ba || (oa == ba && oi < bi)) { ba = oa; bi = oi; bp = op; }
            }
            ba = __shfl_sync(0xffffffffu, ba, 0);
            bi = __shfl_sync(0xffffffffu, bi, 0);
            bp = __shfl_sync(0xffffffffu, bp, 0);
            if (lane == 0) {
                sel_a[r] = ba; sel_i[r] = bi;
                ra[bp] = BIGF;
            }
            __syncwarp();
        }
    }
    __syncthreads();

    if (tid == 0) {
        float d[KSEL];
#pragma unroll
        for (int s = 0; s < KSEL; s++) d[s] = acoshf(sel_a[s]);
        float d0 = d[0];
        float e[KSEL], sum = 0.f;
#pragma unroll
        for (int s = 0; s < KSEL; s++) { e[s] = expf(d0 - d[s]); sum += e[s]; }
        float inv = 1.0f / sum;
#pragma unroll
        for (int s = 0; s < KSEL; s++) out[q * KSEL + s] = e[s] * inv;
    }
    __syncthreads();

    float4* hout = (float4*)(out + (size_t)BQ * KSEL);
    for (int e = tid; e < KSEL * (MAXA / 4); e += 256) {
        int s = e / (MAXA / 4), a4 = e - s * (MAXA / 4);
        const float4* src = (const float4*)(masks + (size_t)sel_i[s] * MAXA);
        hout[((size_t)q * KSEL + s) * (MAXA / 4) + a4] = src[a4];
    }
}

// ============================================================
extern "C" void kernel_launch(void* const* d_in, const int* in_sizes, int n_in,
                              void* d_out, int out_size)
{
    (void)in_sizes; (void)n_in; (void)out_size;
    const float* q_emb  = (const float*)d_in[0];
    const float* m_emb  = (const float*)d_in[1];
    const float* masks  = (const float*)d_in[2];
    const float* W      = (const float*)d_in[3];
    const float* bias   = (const float*)d_in[4];
    float* out = (float*)d_out;

    unsigned *d_mhi, *d_mlo, *d_qhi, *d_qlo;
    float *d_msq, *d_qsq, *d_hm, *d_hq;
    cudaGetSymbolAddress((void**)&d_mhi, g_mem_hi);
    cudaGetSymbolAddress((void**)&d_mlo, g_mem_lo);
    cudaGetSymbolAddress((void**)&d_qhi, g_q_hi);
    cudaGetSymbolAddress((void**)&d_qlo, g_q_lo);
    cudaGetSymbolAddress((void**)&d_msq, g_mem_sq);
    cudaGetSymbolAddress((void**)&d_qsq, g_q_sq);
    cudaGetSymbolAddress((void**)&d_hm,  g_h_mem);
    cudaGetSymbolAddress((void**)&d_hq,  g_h_q);

    cudaFuncSetAttribute(dist_topk_kernel,
                         cudaFuncAttributeMaxDynamicSharedMemorySize, DSMEM_SZ);

    // presplit W only (X split in-kernel — halves X DRAM traffic)
    presplit_w_kernel<<<(256 * 64 + 255) / 256, 256>>>(W);

    // tf32 4-term GEMM + tanh; col-block fastest -> X L2 reuse
    dim3 gm(4, (NM + 127) / 128), gq(4, (BQ + 127) / 128);
    gemm_tanh_kernel<<<gm, 256>>>(m_emb, bias, d_hm, NM);
    gemm_tanh_kernel<<<gq, 256>>>(q_emb, bias, d_hq, BQ);

    // Poincare rescale + |h|^2 + bf16 hi/lo split
    norm_split_kernel<<<(NM + 7) / 8, 256>>>(d_hm, d_mhi, d_mlo, d_msq, NM);
    norm_split_kernel<<<(BQ + 7) / 8, 256>>>(d_hq, d_qhi, d_qlo, d_qsq, BQ);

    dim3 g2(BQ / 128, NSPLIT);
    dist_topk_kernel<<<g2, 256, DSMEM_SZ>>>();

    merge_kernel<<<BQ, 256>>>(masks, out);
}